// round 1
// baseline (speedup 1.0000x reference)
#include <cuda_runtime.h>
#include <math.h>

#define M_TOTAL 32768   // B*H*W = 32*32*32
#define N_ITEMS 2048
#define CDIM    512
#define K_MAX   16

// 256MB scratch for the attention score matrix (alloc via __device__ global, per rules)
__device__ float g_att[(size_t)M_TOTAL * N_ITEMS];

// ---------------------------------------------------------------------------
// Kernel 1: att[n][m] = sum_c q[n][c] * mempool[m][c]
//   q[n][c] = x[b][c][hw] with n = b*1024 + hw  (x is n-contiguous per channel)
//   mempool is [2048][512] row-major (K-contiguous)
// Classic SGEMM tiling: BM=BN=128, BK=16, 256 threads, 8x8 register tile.
// ---------------------------------------------------------------------------
#define BM 128
#define BN 128
#define BK 16
#define BPAD 4   // pad Bs rows to 132 floats (528B, 16B-aligned) for conflict relief

__global__ __launch_bounds__(256) void gemm_att(const float* __restrict__ x,
                                                const float* __restrict__ mempool)
{
    __shared__ float As[BK][BM];          // [c][n]
    __shared__ float Bs[BK][BN + BPAD];   // [c][m]

    const int t  = threadIdx.x;
    const int m0 = blockIdx.x * BM;       // query-row tile (never crosses a batch: 128 | 1024)
    const int n0 = blockIdx.y * BN;       // item tile

    const int b   = m0 >> 10;
    const int hw0 = m0 & 1023;
    const float* xb = x + (size_t)b * CDIM * 1024 + hw0;

    // A-load mapping: float4 along n; 128n x 16c = 512 float4, 2 per thread
    const int a_f = t & 31;               // float4 index along n (0..31)
    const int a_c = t >> 5;               // c (0..7), second pass +8
    // B-load mapping: float4 along c; 128m x 4 c-groups = 512 float4, 2 per thread
    const int b_cg = t & 3;               // c float4 group (0..3)
    const int b_m  = t >> 2;              // m (0..63), second pass +64

    const int tx = t & 15;                // item sub-tile
    const int ty = t >> 4;                // row sub-tile

    float acc[8][8];
    #pragma unroll
    for (int i = 0; i < 8; i++)
        #pragma unroll
        for (int j = 0; j < 8; j++)
            acc[i][j] = 0.f;

    for (int c0 = 0; c0 < CDIM; c0 += BK) {
        // Load A tile: coalesced 512B rows (contiguous along n for fixed c)
        #pragma unroll
        for (int r = 0; r < 2; r++) {
            int c = a_c + r * 8;
            float4 v = *(const float4*)(xb + (size_t)(c0 + c) * 1024 + a_f * 4);
            *(float4*)(&As[c][a_f * 4]) = v;
        }
        // Load B tile: coalesced along c, transpose into smem
        #pragma unroll
        for (int r = 0; r < 2; r++) {
            int m = b_m + r * 64;
            float4 v = *(const float4*)(mempool + (size_t)(n0 + m) * CDIM + c0 + b_cg * 4);
            Bs[b_cg * 4 + 0][m] = v.x;
            Bs[b_cg * 4 + 1][m] = v.y;
            Bs[b_cg * 4 + 2][m] = v.z;
            Bs[b_cg * 4 + 3][m] = v.w;
        }
        __syncthreads();

        #pragma unroll
        for (int kk = 0; kk < BK; kk++) {
            float a[8], bb[8];
            *(float4*)(a)      = *(const float4*)(&As[kk][ty * 8]);
            *(float4*)(a + 4)  = *(const float4*)(&As[kk][ty * 8 + 4]);
            *(float4*)(bb)     = *(const float4*)(&Bs[kk][tx * 8]);
            *(float4*)(bb + 4) = *(const float4*)(&Bs[kk][tx * 8 + 4]);
            #pragma unroll
            for (int i = 0; i < 8; i++)
                #pragma unroll
                for (int j = 0; j < 8; j++)
                    acc[i][j] = fmaf(a[i], bb[j], acc[i][j]);
        }
        __syncthreads();
    }

    // Store C tile (coalesced float4 along items)
    #pragma unroll
    for (int i = 0; i < 8; i++) {
        size_t row = (size_t)(m0 + ty * 8 + i);
        float* p = g_att + row * N_ITEMS + n0 + tx * 8;
        *(float4*)(p)     = make_float4(acc[i][0], acc[i][1], acc[i][2], acc[i][3]);
        *(float4*)(p + 4) = make_float4(acc[i][4], acc[i][5], acc[i][6], acc[i][7]);
    }
}

// ---------------------------------------------------------------------------
// Kernel 2: per-row top-k + softmax + combine + NCHW transpose.
// Block = 256 threads handles 32 consecutive rows (same batch).
// Phase A: 8 lanes/row each keep a sorted top-16 of their 256-score slice,
//          then 8-way shuffle merge -> global top-k -> softmax.
// Phase B/C: combine in 128-column chunks via smem, write coalesced.
// ---------------------------------------------------------------------------
__global__ __launch_bounds__(256) void topk_combine(const float* __restrict__ mempool,
                                                    const int* __restrict__ kptr,
                                                    float* __restrict__ out)
{
    __shared__ float w_s[32][K_MAX];
    __shared__ int   id_s[32][K_MAX];
    __shared__ float out_s[32][133];   // pad 133: bank = (5r+c)%32, conflict-free both ways

    const int t   = threadIdx.x;
    const int n0  = blockIdx.x * 32;
    const int b   = n0 >> 10;
    const int hw0 = n0 & 1023;

    int kval = kptr ? kptr[0] : 8;
    if (kval < 1) kval = 1;
    if (kval > K_MAX) kval = K_MAX;

    // ---- Phase A: streaming top-16 per lane ----
    const int g = t >> 3;     // row in block (0..31)
    const int j = t & 7;      // lane within row-group
    const int n = n0 + g;
    const float4* row4 = (const float4*)(g_att + (size_t)n * N_ITEMS);

    float v[K_MAX];
    int   id[K_MAX];
    #pragma unroll
    for (int p = 0; p < K_MAX; p++) { v[p] = -INFINITY; id[p] = 0; }

    #pragma unroll 4
    for (int i = 0; i < N_ITEMS / 32; i++) {      // 64 float4 per lane
        float4 s4 = row4[j + 8 * i];
        int base = (j + 8 * i) * 4;
        float ss[4] = {s4.x, s4.y, s4.z, s4.w};
        #pragma unroll
        for (int u = 0; u < 4; u++) {
            float s = ss[u];
            int  si = base + u;
            if (s > v[K_MAX - 1]) {
                #pragma unroll
                for (int p = 0; p < K_MAX; p++) {
                    if (s > v[p]) {
                        float tv = v[p]; int ti = id[p];
                        v[p] = s;  id[p] = si;
                        s = tv;    si = ti;
                    }
                }
            }
        }
    }

    // ---- 8-way sorted-list merge via shuffles (width 8) ----
    float mg_v[K_MAX];
    int   mg_i[K_MAX];
    #pragma unroll
    for (int it = 0; it < K_MAX; it++) {
        mg_v[it] = 0.f; mg_i[it] = 0;
        if (it < kval) {
            float bv = v[0]; int bi = id[0]; int bl = j;
            #pragma unroll
            for (int off = 4; off > 0; off >>= 1) {
                float ov = __shfl_xor_sync(0xffffffffu, bv, off, 8);
                int   oi = __shfl_xor_sync(0xffffffffu, bi, off, 8);
                int   ol = __shfl_xor_sync(0xffffffffu, bl, off, 8);
                if (ov > bv || (ov == bv && ol < bl)) { bv = ov; bi = oi; bl = ol; }
            }
            mg_v[it] = bv; mg_i[it] = bi;
            if (bl == j) {  // owner pops its head
                #pragma unroll
                for (int p = 0; p < K_MAX - 1; p++) { v[p] = v[p + 1]; id[p] = id[p + 1]; }
                v[K_MAX - 1] = -INFINITY;
            }
        }
    }

    // ---- softmax; lane 0 of each group publishes ----
    if (j == 0) {
        float mx = mg_v[0];   // extraction order is descending
        float e[K_MAX];
        float sum = 0.f;
        #pragma unroll
        for (int it = 0; it < K_MAX; it++) {
            float ev = 0.f;
            if (it < kval) { ev = __expf(mg_v[it] - mx); sum += ev; }
            e[it] = ev;
        }
        float inv = 1.f / sum;
        #pragma unroll
        for (int it = 0; it < K_MAX; it++) {
            w_s[g][it]  = e[it] * inv;
            id_s[g][it] = mg_i[it];
        }
    }
    __syncthreads();

    // ---- Phase B/C: combine + transposed write, 128-column chunks ----
    const int wrp  = t >> 5;
    const int lane = t & 31;
    const size_t obase = (size_t)b * CDIM * 1024 + hw0;

    for (int cc = 0; cc < CDIM; cc += 128) {
        // combine: warp w handles rows 4w..4w+3; lanes cover columns -> coalesced mempool reads
        #pragma unroll
        for (int rr = 0; rr < 4; rr++) {
            int r = wrp * 4 + rr;
            #pragma unroll
            for (int cl = 0; cl < 4; cl++) {
                int c = lane + cl * 32;
                float acc = 0.f;
                #pragma unroll
                for (int i = 0; i < K_MAX; i++) {
                    if (i < kval)
                        acc += w_s[r][i] * __ldg(&mempool[(size_t)id_s[r][i] * CDIM + cc + c]);
                }
                out_s[r][c] = acc;
            }
        }
        __syncthreads();

        // transposed write: 32 consecutive hw per (b,c) -> 128B coalesced stores
        const int r2 = t & 31;
        const int cg = t >> 5;
        #pragma unroll
        for (int jj = 0; jj < 16; jj++) {
            int c = cg + 8 * jj;
            out[obase + (size_t)(cc + c) * 1024 + r2] = out_s[r2][c];
        }
        __syncthreads();
    }
}

// ---------------------------------------------------------------------------
extern "C" void kernel_launch(void* const* d_in, const int* in_sizes, int n_in,
                              void* d_out, int out_size)
{
    const float* x       = (const float*)d_in[0];
    const float* mempool = (const float*)d_in[1];
    const int*   kptr    = (n_in >= 3) ? (const int*)d_in[2] : nullptr;
    float*       out     = (float*)d_out;

    dim3 g1(M_TOTAL / BM, N_ITEMS / BN);   // (256, 16)
    gemm_att<<<g1, 256>>>(x, mempool);
    topk_combine<<<M_TOTAL / 32, 256>>>(mempool, kptr, out);
}